// round 15
// baseline (speedup 1.0000x reference)
#include <cuda_runtime.h>
#include <cuda_fp16.h>
#include <cstdint>

// Problem constants
#define BB 2
#define HH 256
#define WW 256
#define CC 256
#define WS 8
#define SHIFT 4
#define NH 8
#define HD 32
#define OUTC 256
#define NWIN 1024
#define PP 64
#define MROWS 131072

// Scratch (device globals)
__device__ __half g_embh[2u*131072u*256u];          // rolled+windowed emb, fp16 [s][R][k]
__device__ __half g_qkvh[2u*3u*BB*NWIN*NH*PP*HD];   // [s][qkv][b][win][head][p][d] fp16
__device__ __half g_attnh[2u*BB*NWIN*PP*CC];        // [s][b][win][p][C] fp16
__device__ float  g_bias[2*NH*PP*PP];
// Weights packed in per-lane FRAGMENT order (linear order same as R14):
//   per (s,cb): [c][k16][jp(8)][lane(32)] x uint4{b00,b10,b01,b11}
__device__ __half g_wh[524288];

__device__ __forceinline__ uint32_t f22u(float a, float b) {
    __half2 h = __floats2half2_rn(a, b);
    return *reinterpret_cast<uint32_t*>(&h);
}

__device__ __forceinline__ void mma_f16(float c[4],
                                        uint32_t a0, uint32_t a1, uint32_t a2, uint32_t a3,
                                        uint32_t b0, uint32_t b1) {
    asm volatile(
        "mma.sync.aligned.m16n8k16.row.col.f32.f16.f16.f32 "
        "{%0,%1,%2,%3}, {%4,%5,%6,%7}, {%8,%9}, {%0,%1,%2,%3};"
        : "+f"(c[0]), "+f"(c[1]), "+f"(c[2]), "+f"(c[3])
        : "r"(a0), "r"(a1), "r"(a2), "r"(a3), "r"(b0), "r"(b1));
}

__device__ __forceinline__ void ldsm4(uint32_t& r0, uint32_t& r1, uint32_t& r2, uint32_t& r3,
                                      uint32_t addr) {
    asm volatile("ldmatrix.sync.aligned.m8n8.x4.shared.b16 {%0,%1,%2,%3}, [%4];"
                 : "=r"(r0), "=r"(r1), "=r"(r2), "=r"(r3) : "r"(addr));
}
__device__ __forceinline__ void ldsm4t(uint32_t& r0, uint32_t& r1, uint32_t& r2, uint32_t& r3,
                                       uint32_t addr) {
    asm volatile("ldmatrix.sync.aligned.m8n8.x4.trans.shared.b16 {%0,%1,%2,%3}, [%4];"
                 : "=r"(r0), "=r"(r1), "=r"(r2), "=r"(r3) : "r"(addr));
}
__device__ __forceinline__ uint32_t sm_a(const void* p) {
    return (uint32_t)__cvta_generic_to_shared(p);
}
__device__ __forceinline__ void cpa16(uint32_t saddr, const void* g) {
    asm volatile("cp.async.cg.shared.global [%0], [%1], 16;"
                 :: "r"(saddr), "l"(g));
}
#define CP_COMMIT() asm volatile("cp.async.commit_group;")
__device__ __forceinline__ void lds128(uint4& v, uint32_t addr) {
    asm volatile("ld.shared.v4.u32 {%0,%1,%2,%3}, [%4];"
                 : "=r"(v.x), "=r"(v.y), "=r"(v.z), "=r"(v.w) : "r"(addr));
}

#define APH 40     // attn smem pitch (halves)
#define AP2 72     // gemm A smem pitch (halves): 144B rows, conflict-free ldmatrix
#define ASTG2 18432   // A stage: 128 x 72 halves
#define BSTG2 16384   // B stage: fragment-packed chunk of 64 k
#define STAGE_BYTES (ASTG2 + BSTG2)   // 34816
#define NSTAGE 3
#define GEMM_SMEM  (NSTAGE * STAGE_BYTES)

// ---------------------------------------------------------------------------
// Kernel 0a: bias table
// ---------------------------------------------------------------------------
__global__ void bias_kernel(const float* __restrict__ rel1,
                            const float* __restrict__ rel2)
{
    int idx = blockIdx.x * blockDim.x + threadIdx.x;
    int s = idx >> 15, head = (idx >> 12) & 7, p = (idx >> 6) & 63, q = idx & 63;
    const float* rel = s ? rel2 : rel1;
    int a = (p >> 3) - (q >> 3) + 7;
    int b = (p & 7) - (q & 7) + 7;
    g_bias[idx] = rel[head * 225 + a * 15 + b];
}

// ---------------------------------------------------------------------------
// Kernel 0b: pack weights into fp16 fragment order (unchanged from R14).
// ---------------------------------------------------------------------------
__global__ void wpack_kernel(const float* __restrict__ Wqkv1,
                             const float* __restrict__ Wqkv2,
                             const float* __restrict__ Wo1,
                             const float* __restrict__ Wo2)
{
    int idx = blockIdx.x * blockDim.x + threadIdx.x;   // 0..524287
    const float* W;
    int N, cb, r;
    if (idx < 393216) {
        int scb = idx >> 15;
        r = idx & 32767;
        int s = scb / 6; cb = scb % 6;
        W = s ? Wqkv2 : Wqkv1; N = 768;
    } else {
        int t = idx - 393216;
        int scb = t >> 15;
        r = t & 32767;
        int s = scb >> 1; cb = scb & 1;
        W = s ? Wo2 : Wo1; N = 256;
    }
    int c    = r >> 12;
    int r2   = r & 4095;
    int k16  = r2 >> 11;
    int r3   = r2 & 2047;
    int jp   = r3 >> 8;
    int r4   = r3 & 255;
    int lane = r4 >> 3;
    int e    = r4 & 7;
    int g = lane >> 2, t4 = lane & 3;
    int reg = e >> 1, h = e & 1;
    int k = c * 32 + k16 * 16 + ((reg & 1) ? 8 : 0) + 2 * t4 + h;
    int n = cb * 128 + jp * 16 + ((reg & 2) ? 8 : 0) + g;
    g_wh[idx] = __float2half_rn(W[k * N + n]);
}

// ---------------------------------------------------------------------------
// Kernel 0c: emb -> fp16 with fused roll + window gather ([s][R][k] rows)
// ---------------------------------------------------------------------------
__global__ __launch_bounds__(256)
void embh_kernel(const float* __restrict__ emb1, const float* __restrict__ emb2)
{
    unsigned idx = blockIdx.x * 256 + threadIdx.x;   // 8 halves each
    int s = idx >> 22;
    unsigned r = idx & 4194303u;
    unsigned R = r >> 5, gi = r & 31;
    int p_ = R & 63, win_ = (R >> 6) & 1023, b_ = R >> 16;
    int hs = (((win_ >> 5) << 3) + (p_ >> 3) + SHIFT) & 255;
    int ws = ((win_ & 31) << 3) + (p_ & 7);
    const float* src = (s ? emb2 : emb1)
                     + ((((size_t)b_ * HH + hs) * WW + ws) * CC) + gi * 8;
    float4 f0 = *reinterpret_cast<const float4*>(src);
    float4 f1 = *reinterpret_cast<const float4*>(src + 4);
    uint4 o;
    o.x = f22u(f0.x, f0.y); o.y = f22u(f0.z, f0.w);
    o.z = f22u(f1.x, f1.y); o.w = f22u(f1.z, f1.w);
    *reinterpret_cast<uint4*>(&g_embh[((size_t)s << 25) + (size_t)R * 256 + gi * 8]) = o;
}

// ---------------------------------------------------------------------------
// Kernel 1: QKV GEMM. Chunks of K=64 (4 chunks), 3-stage cp.async.
// A via ldmatrix (pitch 72), B via per-k16 fragment LDS.128.
// ---------------------------------------------------------------------------
__global__ __launch_bounds__(256)
void qkv_mma(const float* __restrict__ bqkv1, const float* __restrict__ bqkv2)
{
    extern __shared__ __align__(16) __half sh[];
    const int s = blockIdx.z;
    const float* __restrict__ bq = s ? bqkv2 : bqkv1;
    const int colBlock = blockIdx.x;     // 0..5
    const int rowBlock = blockIdx.y;     // 0..1023
    const int tid  = threadIdx.x;
    const int wid  = tid >> 5;
    const int lane = tid & 31;
    const int g    = lane >> 2;
    const int t4   = lane & 3;
    const int lrow = lane & 7;

    const __half* aBase = g_embh + ((size_t)s << 25) + (size_t)rowBlock * 128 * 256;
    const __half* bBase = g_wh + (size_t)(s * 6 + colBlock) * 32768;

    const uint32_t smemBase = sm_a(sh);
    // A cp.async mapping: 1024 16B-units/chunk; unit = tid + i*256
    uint32_t aSm[4]; int aGm[4];
#pragma unroll
    for (int i = 0; i < 4; ++i) {
        int unit = tid + i * 256;
        int r = unit >> 3, j = unit & 7;
        aSm[i] = (uint32_t)(r * 9 + j) * 16;
        aGm[i] = r * 256 + j * 8;
    }

    const int wrb = (wid & 3) * 32;
    const int wq  = wid >> 2;
    const uint32_t aOff0 = ((wrb + lrow + ((lane >> 3) & 1) * 8) * AP2 + ((lane >> 4) & 1) * 8) * 2;
    const uint32_t aOff1 = aOff0 + 16 * AP2 * 2;
    const uint32_t bfOff = ASTG2 + ((wq * 4) * 32 + lane) * 16;   // +k16*4096 +jpLocal*512

#define QISSUE(c, st) do {                                                        \
    uint32_t ab = smemBase + (st) * STAGE_BYTES;                                  \
    uint32_t bb = ab + ASTG2;                                                     \
    cpa16(ab + aSm[0], aBase + aGm[0] + (c) * 64);                                \
    cpa16(ab + aSm[1], aBase + aGm[1] + (c) * 64);                                \
    cpa16(ab + aSm[2], aBase + aGm[2] + (c) * 64);                                \
    cpa16(ab + aSm[3], aBase + aGm[3] + (c) * 64);                                \
    cpa16(bb + (tid          ) * 16, bBase + (size_t)(c) * 8192 + (tid          ) * 8); \
    cpa16(bb + (tid + 256    ) * 16, bBase + (size_t)(c) * 8192 + (tid + 256    ) * 8); \
    cpa16(bb + (tid + 512    ) * 16, bBase + (size_t)(c) * 8192 + (tid + 512    ) * 8); \
    cpa16(bb + (tid + 768    ) * 16, bBase + (size_t)(c) * 8192 + (tid + 768    ) * 8); \
    CP_COMMIT();                                                                  \
} while (0)

    float acc[2][8][4];
#pragma unroll
    for (int mi = 0; mi < 2; mi++)
#pragma unroll
        for (int nj = 0; nj < 8; nj++)
#pragma unroll
            for (int k = 0; k < 4; k++) acc[mi][nj][k] = 0.f;

    QISSUE(0, 0);
    QISSUE(1, 1);

#pragma unroll
    for (int c = 0; c < 4; ++c) {
        const int st = c % NSTAGE;
        if (c < 3) asm volatile("cp.async.wait_group 1;");
        else       asm volatile("cp.async.wait_group 0;");
        __syncthreads();
        if (c < 2) QISSUE(c + 2, (c + 2) % NSTAGE);

        const uint32_t stb = smemBase + st * STAGE_BYTES;
#pragma unroll
        for (int k16 = 0; k16 < 4; ++k16) {
            uint4 bf[4];
#pragma unroll
            for (int jp = 0; jp < 4; ++jp)
                lds128(bf[jp], stb + bfOff + k16 * 4096 + jp * 512);
            uint32_t a0[2], a1[2], a2[2], a3[2];
            ldsm4(a0[0], a1[0], a2[0], a3[0], stb + aOff0 + k16 * 32);
            ldsm4(a0[1], a1[1], a2[1], a3[1], stb + aOff1 + k16 * 32);
#pragma unroll
            for (int jp = 0; jp < 4; ++jp) {
                const uint4 b = bf[jp];
                mma_f16(acc[0][2*jp],   a0[0], a1[0], a2[0], a3[0], b.x, b.y);
                mma_f16(acc[0][2*jp+1], a0[0], a1[0], a2[0], a3[0], b.z, b.w);
                mma_f16(acc[1][2*jp],   a0[1], a1[1], a2[1], a3[1], b.x, b.y);
                mma_f16(acc[1][2*jp+1], a0[1], a1[1], a2[1], a3[1], b.z, b.w);
            }
        }
    }
#undef QISSUE

    // Epilogue: add bias, convert fp16, scatter to q/k/v layout
    const int wcb = wq * 64;
#pragma unroll
    for (int mi = 0; mi < 2; mi++) {
#pragma unroll
        for (int h = 0; h < 2; h++) {
            int r  = rowBlock * 128 + wrb + mi * 16 + g + 8 * h;
            int pr = r & 63, wr = (r >> 6) & 1023, br = r >> 16;
#pragma unroll
            for (int nj = 0; nj < 8; nj++) {
                int n = colBlock * 128 + wcb + nj * 8 + t4 * 2;
                float vx = acc[mi][nj][h * 2 + 0] + bq[n];
                float vy = acc[mi][nj][h * 2 + 1] + bq[n + 1];
                int qkvi = n >> 8, head = (n >> 5) & 7, d = n & 31;
                size_t idx = ((((size_t)(s * 3 + qkvi) * BB + br) * NWIN + wr) * NH + head)
                                 * ((size_t)PP * HD)
                             + (size_t)pr * HD + d;
                __half2 hv = __floats2half2_rn(vx, vy);
                *reinterpret_cast<__half2*>(&g_qkvh[idx]) = hv;
            }
        }
    }
}

// ---------------------------------------------------------------------------
// Kernel 2: windowed cross-attention, register softmax + ldmatrix (unchanged).
// ---------------------------------------------------------------------------
__global__ __launch_bounds__(128)
void attn_mma()
{
    const int s    = blockIdx.z;
    const int head = blockIdx.y;
    const int bw   = blockIdx.x;
    const int b    = bw >> 10;
    const int win  = bw & 1023;
    const int os   = 1 - s;

    __shared__ __align__(16) __half qs[64 * APH];
    __shared__ __align__(16) __half ks[64 * APH];
    __shared__ __align__(16) __half vs[64 * APH];   // [p][d]

    const int tid = threadIdx.x;
    const size_t tile = (size_t)PP * HD;
    const size_t qbase = (((((size_t)s  * 3 + 0) * BB + b) * NWIN + win) * NH + head) * tile;
    const size_t kbase = (((((size_t)os * 3 + 1) * BB + b) * NWIN + win) * NH + head) * tile;
    const size_t vbase = (((((size_t)os * 3 + 2) * BB + b) * NWIN + win) * NH + head) * tile;

    {
        const uint4* qg = reinterpret_cast<const uint4*>(&g_qkvh[qbase]);
        const uint4* kg = reinterpret_cast<const uint4*>(&g_qkvh[kbase]);
        const uint4* vg = reinterpret_cast<const uint4*>(&g_qkvh[vbase]);
        int u  = tid * 2;
        int p  = tid >> 1;
        int d0 = (tid & 1) * 16;
        uint4 x0 = qg[u], x1 = qg[u + 1];
        *reinterpret_cast<uint4*>(&qs[p * APH + d0])     = x0;
        *reinterpret_cast<uint4*>(&qs[p * APH + d0 + 8]) = x1;
        uint4 y0 = kg[u], y1 = kg[u + 1];
        *reinterpret_cast<uint4*>(&ks[p * APH + d0])     = y0;
        *reinterpret_cast<uint4*>(&ks[p * APH + d0 + 8]) = y1;
        uint4 z0 = vg[u], z1 = vg[u + 1];
        *reinterpret_cast<uint4*>(&vs[p * APH + d0])     = z0;
        *reinterpret_cast<uint4*>(&vs[p * APH + d0 + 8]) = z1;
    }
    __syncthreads();

    const int w    = tid >> 5;
    const int lane = tid & 31;
    const int g    = lane >> 2;
    const int t4   = lane & 3;
    const int r0   = w * 16;
    const int lrow = lane & 7;

    uint32_t qAddr = sm_a(&qs[(r0 + lrow + ((lane >> 3) & 1) * 8) * APH + ((lane >> 4) & 1) * 8]);
    uint32_t kAddr = sm_a(&ks[(lrow + ((lane >> 4) & 1) * 8) * APH + ((lane >> 3) & 1) * 8]);
    uint32_t vAddr = sm_a(&vs[(lrow + ((lane >> 3) & 1) * 8) * APH + ((lane >> 4) & 1) * 8]);

    float c1[8][4];
#pragma unroll
    for (int nj = 0; nj < 8; nj++)
#pragma unroll
        for (int k = 0; k < 4; k++) c1[nj][k] = 0.f;

#pragma unroll
    for (int k16 = 0; k16 < 2; ++k16) {
        uint32_t a0, a1, a2, a3;
        ldsm4(a0, a1, a2, a3, qAddr + k16 * 32);
#pragma unroll
        for (int jp = 0; jp < 4; ++jp) {
            uint32_t b00, b10, b01, b11;
            ldsm4(b00, b10, b01, b11, kAddr + jp * (16 * APH * 2) + k16 * 32);
            mma_f16(c1[2*jp],   a0, a1, a2, a3, b00, b10);
            mma_f16(c1[2*jp+1], a0, a1, a2, a3, b01, b11);
        }
    }

    const size_t bbias = ((size_t)s * NH + head) * 4096;
    const bool mh = ((win >> 5) == 31);
    const bool mw = ((win & 31) == 31);
    const float scale = 0.17677669529663687f;
    const int rowA = r0 + g, rowB = rowA + 8;
    const int ipA = rowA >> 3, jpA = rowA & 7;
    const int ipB = rowB >> 3, jpB = rowB & 7;
    const int jq0 = 2 * t4, jq1 = 2 * t4 + 1;

    float mA = -1e30f, mB = -1e30f;
#pragma unroll
    for (int nj = 0; nj < 8; nj++) {
        int col = nj * 8 + 2 * t4;
        int iq  = col >> 3;
        float2 bA = *reinterpret_cast<const float2*>(&g_bias[bbias + rowA * 64 + col]);
        float2 bB = *reinterpret_cast<const float2*>(&g_bias[bbias + rowB * 64 + col]);
        bool hA = mh && ((ipA < 4) != (iq < 4));
        bool hB = mh && ((ipB < 4) != (iq < 4));
        bool w0A = hA || (mw && ((jpA < 4) != (jq0 < 4)));
        bool w1A = hA || (mw && ((jpA < 4) != (jq1 < 4)));
        bool w0B = hB || (mw && ((jpB < 4) != (jq0 < 4)));
        bool w1B = hB || (mw && ((jpB < 4) != (jq1 < 4)));
        float v0 = w0A ? -1e30f : c1[nj][0] * scale + bA.x;
        float v1 = w1A ? -1e30f : c1[nj][1] * scale + bA.y;
        float v2 = w0B ? -1e30f : c1[nj][2] * scale + bB.x;
        float v3 = w1B ? -1e30f : c1[nj][3] * scale + bB.y;
        c1[nj][0] = v0; c1[nj][1] = v1; c1[nj][2] = v2; c1[nj][3] = v3;
        mA = fmaxf(mA, fmaxf(v0, v1));
        mB = fmaxf(mB, fmaxf(v2, v3));
    }
    mA = fmaxf(mA, __shfl_xor_sync(0xffffffffu, mA, 1));
    mA = fmaxf(mA, __shfl_xor_sync(0xffffffffu, mA, 2));
    mB = fmaxf(mB, __shfl_xor_sync(0xffffffffu, mB, 1));
    mB = fmaxf(mB, __shfl_xor_sync(0xffffffffu, mB, 2));

    float sA = 0.f, sB = 0.f;
#pragma unroll
    for (int nj = 0; nj < 8; nj++) {
        float e0 = __expf(c1[nj][0] - mA);
        float e1 = __expf(c1[nj][1] - mA);
        float e2 = __expf(c1[nj][2] - mB);
        float e3 = __expf(c1[nj][3] - mB);
        c1[nj][0] = e0; c1[nj][1] = e1; c1[nj][2] = e2; c1[nj][3] = e3;
        sA += e0 + e1; sB += e2 + e3;
    }
    sA += __shfl_xor_sync(0xffffffffu, sA, 1);
    sA += __shfl_xor_sync(0xffffffffu, sA, 2);
    sB += __shfl_xor_sync(0xffffffffu, sB, 1);
    sB += __shfl_xor_sync(0xffffffffu, sB, 2);
    const float invA = 1.f / sA, invB = 1.f / sB;

    float c2[4][4];
#pragma unroll
    for (int nj = 0; nj < 4; nj++)
#pragma unroll
        for (int k = 0; k < 4; k++) c2[nj][k] = 0.f;

#pragma unroll
    for (int k16 = 0; k16 < 4; ++k16) {
        uint32_t a0 = f22u(c1[2*k16][0]   * invA, c1[2*k16][1]   * invA);
        uint32_t a1 = f22u(c1[2*k16][2]   * invB, c1[2*k16][3]   * invB);
        uint32_t a2 = f22u(c1[2*k16+1][0] * invA, c1[2*k16+1][1] * invA);
        uint32_t a3 = f22u(c1[2*k16+1][2] * invB, c1[2*k16+1][3] * invB);
#pragma unroll
        for (int jp = 0; jp < 2; ++jp) {
            uint32_t b00, b10, b01, b11;
            ldsm4t(b00, b10, b01, b11, vAddr + k16 * (16 * APH * 2) + jp * 32);
            mma_f16(c2[2*jp],   a0, a1, a2, a3, b00, b10);
            mma_f16(c2[2*jp+1], a0, a1, a2, a3, b01, b11);
        }
    }

    const size_t obase = (size_t)s * ((size_t)BB * NWIN * PP * CC)
                       + (((size_t)b * NWIN + win) * PP) * CC
                       + (size_t)head * HD;
#pragma unroll
    for (int nj = 0; nj < 4; nj++) {
#pragma unroll
        for (int h2 = 0; h2 < 2; h2++) {
            int row = r0 + g + 8 * h2;
            int col = nj * 8 + t4 * 2;
            __half2 hv = __floats2half2_rn(c2[nj][h2 * 2 + 0], c2[nj][h2 * 2 + 1]);
            *reinterpret_cast<__half2*>(&g_attnh[obase + (size_t)row * CC + col]) = hv;
        }
    }
}

// ---------------------------------------------------------------------------
// Kernel 3: output projection. Chunk-64, same structure as qkv.
// ---------------------------------------------------------------------------
__global__ __launch_bounds__(256)
void proj_mma(const float* __restrict__ bo1, const float* __restrict__ bo2,
              float* __restrict__ out)
{
    extern __shared__ __align__(16) __half sh[];
    const int s = blockIdx.z;
    const float* __restrict__ bo = s ? bo2 : bo1;
    float* __restrict__ dst = out + (size_t)s * ((size_t)BB * HH * WW * OUTC);
    const int colBlock = blockIdx.x;     // 0..1
    const int rowBlock = blockIdx.y;     // 0..1023
    const int tid  = threadIdx.x;
    const int wid  = tid >> 5;
    const int lane = tid & 31;
    const int g    = lane >> 2;
    const int t4   = lane & 3;
    const int lrow = lane & 7;

    const __half* aBase = g_attnh + (size_t)s * ((size_t)BB * NWIN * PP * CC)
                        + (size_t)rowBlock * 128 * 256;
    const __half* bBase = g_wh + 393216 + (size_t)(s * 2 + colBlock) * 32768;

    const uint32_t smemBase = sm_a(sh);
    uint32_t aSm[4]; int aGm[4];
#pragma unroll
    for (int i = 0; i < 4; ++i) {
        int unit = tid + i * 256;
        int r = unit >> 3, j = unit & 7;
        aSm[i] = (uint32_t)(r * 9 + j) * 16;
        aGm[i] = r * 256 + j * 8;
    }

    const int wrb = (wid & 3) * 32;
    const int wq  = wid >> 2;
    const uint32_t aOff0 = ((wrb + lrow + ((lane >> 3) & 1) * 8) * AP2 + ((lane >> 4) & 1) * 8) * 2;
    const uint32_t aOff1 = aOff0 + 16 * AP2 * 2;
    const uint32_t bfOff = ASTG2 + ((wq * 4) * 32 + lane) * 16;

#define PISSUE(c, st) do {                                                        \
    uint32_t ab = smemBase + (st) * STAGE_BYTES;                                  \
    uint32_t bb = ab + ASTG2;                                                     \
    cpa16(ab + aSm[0], aBase + aGm[0] + (c) * 64);                                \
    cpa16(ab + aSm[1], aBase + aGm[1] + (c) * 64);                                \
    cpa16(ab + aSm[2], aBase + aGm[2] + (c) * 64);                                \
    cpa16(ab + aSm[3], aBase + aGm[3] + (c) * 64);                                \
    cpa16(bb + (tid      ) * 16, bBase + (size_t)(c) * 8192 + (tid      ) * 8);   \
    cpa16(bb + (tid + 256) * 16, bBase + (size_t)(c) * 8192 + (tid + 256) * 8);   \
    cpa16(bb + (tid + 512) * 16, bBase + (size_t)(c) * 8192 + (tid + 512) * 8);   \
    cpa16(bb + (tid + 768) * 16, bBase + (size_t)(c) * 8192 + (tid + 768) * 8);   \
    CP_COMMIT();                                                                  \
} while (0)

    float acc[2][8][4];
#pragma unroll
    for (int mi = 0; mi < 2; mi++)
#pragma unroll
        for (int nj = 0; nj < 8; nj++)
#pragma unroll
            for (int k = 0; k < 4; k++) acc[mi][nj][k] = 0.f;

    PISSUE(0, 0);
    PISSUE(1, 1);

#pragma unroll
    for (int c = 0; c < 4; ++c) {
        const int st = c % NSTAGE;
        if (c < 3) asm volatile("cp.async.wait_group 1;");
        else       asm volatile("cp.async.wait_group 0;");
        __syncthreads();
        if (c < 2) PISSUE(c + 2, (c + 2) % NSTAGE);

        const uint32_t stb = smemBase + st * STAGE_BYTES;
#pragma unroll
        for (int k16 = 0; k16 < 4; ++k16) {
            uint4 bf[4];
#pragma unroll
            for (int jp = 0; jp < 4; ++jp)
                lds128(bf[jp], stb + bfOff + k16 * 4096 + jp * 512);
            uint32_t a0[2], a1[2], a2[2], a3[2];
            ldsm4(a0[0], a1[0], a2[0], a3[0], stb + aOff0 + k16 * 32);
            ldsm4(a0[1], a1[1], a2[1], a3[1], stb + aOff1 + k16 * 32);
#pragma unroll
            for (int jp = 0; jp < 4; ++jp) {
                const uint4 b = bf[jp];
                mma_f16(acc[0][2*jp],   a0[0], a1[0], a2[0], a3[0], b.x, b.y);
                mma_f16(acc[0][2*jp+1], a0[0], a1[0], a2[0], a3[0], b.z, b.w);
                mma_f16(acc[1][2*jp],   a0[1], a1[1], a2[1], a3[1], b.x, b.y);
                mma_f16(acc[1][2*jp+1], a0[1], a1[1], a2[1], a3[1], b.z, b.w);
            }
        }
    }
#undef PISSUE

    // Epilogue: unwindow + roll scatter (fp32 output)
    const int wcb = wq * 64;
#pragma unroll
    for (int mi = 0; mi < 2; mi++) {
#pragma unroll
        for (int h = 0; h < 2; h++) {
            int r  = rowBlock * 128 + wrb + mi * 16 + g + 8 * h;
            int pr = r & 63, wr = (r >> 6) & 1023, br = r >> 16;
            int hout = (((wr >> 5) << 3) + (pr >> 3) + SHIFT) & 255;
            int wout = ((wr & 31) << 3) + (pr & 7);
            size_t rowbase = (((size_t)br * HH + hout) * WW + wout) * OUTC;
#pragma unroll
            for (int nj = 0; nj < 8; nj++) {
                int n = colBlock * 128 + wcb + nj * 8 + t4 * 2;
                float2 v;
                v.x = acc[mi][nj][h * 2 + 0] + bo[n];
                v.y = acc[mi][nj][h * 2 + 1] + bo[n + 1];
                *reinterpret_cast<float2*>(&dst[rowbase + n]) = v;
            }
        }
    }
}

// ---------------------------------------------------------------------------
// Launch
// ---------------------------------------------------------------------------
extern "C" void kernel_launch(void* const* d_in, const int* in_sizes, int n_in,
                              void* d_out, int out_size)
{
    const float* emb1  = (const float*)d_in[0];
    const float* emb2  = (const float*)d_in[1];
    const float* Wqkv1 = (const float*)d_in[2];
    const float* bqkv1 = (const float*)d_in[3];
    const float* Wqkv2 = (const float*)d_in[4];
    const float* bqkv2 = (const float*)d_in[5];
    const float* rel1  = (const float*)d_in[6];
    const float* rel2  = (const float*)d_in[7];
    const float* Wo1   = (const float*)d_in[8];
    const float* bo1   = (const float*)d_in[9];
    const float* Wo2   = (const float*)d_in[10];
    const float* bo2   = (const float*)d_in[11];
    float* out = (float*)d_out;
    (void)in_sizes; (void)n_in; (void)out_size;

    cudaFuncSetAttribute(qkv_mma,  cudaFuncAttributeMaxDynamicSharedMemorySize, GEMM_SMEM);
    cudaFuncSetAttribute(proj_mma, cudaFuncAttributeMaxDynamicSharedMemorySize, GEMM_SMEM);

    bias_kernel<<<256, 256>>>(rel1, rel2);
    wpack_kernel<<<2048, 256>>>(Wqkv1, Wqkv2, Wo1, Wo2);
    embh_kernel<<<32768, 256>>>(emb1, emb2);

    dim3 gq(6, 1024, 2);
    qkv_mma<<<gq, 256, GEMM_SMEM>>>(bqkv1, bqkv2);

    dim3 ga(2048, 8, 2);
    attn_mma<<<ga, 128>>>();

    dim3 gp(2, 1024, 2);
    proj_mma<<<gp, 256, GEMM_SMEM>>>(bo1, bo2, out);
}

// round 16
// speedup vs baseline: 1.1443x; 1.1443x over previous
#include <cuda_runtime.h>
#include <cuda_fp16.h>
#include <cstdint>

// Problem constants
#define BB 2
#define HH 256
#define WW 256
#define CC 256
#define WS 8
#define SHIFT 4
#define NH 8
#define HD 32
#define OUTC 256
#define NWIN 1024
#define PP 64
#define MROWS 131072

// Scratch (device globals)
__device__ __half g_embh[2u*131072u*256u];          // rolled+windowed emb, fp16 [s][R][k]
__device__ __half g_qkvh[2u*3u*BB*NWIN*NH*PP*HD];   // [s][qkv][b][win][head][p][d] fp16
__device__ __half g_attnh[2u*BB*NWIN*PP*CC];        // [s][b][win][p][C] fp16
__device__ float  g_bias[2*NH*PP*PP];
// Weights packed in per-lane FRAGMENT order (linear order same as R14):
//   per (s,cb): [c][k16][jp(8)][lane(32)] x uint4{b00,b10,b01,b11}
__device__ __half g_wh[524288];

__device__ __forceinline__ uint32_t f22u(float a, float b) {
    __half2 h = __floats2half2_rn(a, b);
    return *reinterpret_cast<uint32_t*>(&h);
}

__device__ __forceinline__ void mma_f16(float c[4],
                                        uint32_t a0, uint32_t a1, uint32_t a2, uint32_t a3,
                                        uint32_t b0, uint32_t b1) {
    asm volatile(
        "mma.sync.aligned.m16n8k16.row.col.f32.f16.f16.f32 "
        "{%0,%1,%2,%3}, {%4,%5,%6,%7}, {%8,%9}, {%0,%1,%2,%3};"
        : "+f"(c[0]), "+f"(c[1]), "+f"(c[2]), "+f"(c[3])
        : "r"(a0), "r"(a1), "r"(a2), "r"(a3), "r"(b0), "r"(b1));
}

__device__ __forceinline__ void ldsm4(uint32_t& r0, uint32_t& r1, uint32_t& r2, uint32_t& r3,
                                      uint32_t addr) {
    asm volatile("ldmatrix.sync.aligned.m8n8.x4.shared.b16 {%0,%1,%2,%3}, [%4];"
                 : "=r"(r0), "=r"(r1), "=r"(r2), "=r"(r3) : "r"(addr));
}
__device__ __forceinline__ void ldsm4t(uint32_t& r0, uint32_t& r1, uint32_t& r2, uint32_t& r3,
                                       uint32_t addr) {
    asm volatile("ldmatrix.sync.aligned.m8n8.x4.trans.shared.b16 {%0,%1,%2,%3}, [%4];"
                 : "=r"(r0), "=r"(r1), "=r"(r2), "=r"(r3) : "r"(addr));
}
__device__ __forceinline__ uint32_t sm_a(const void* p) {
    return (uint32_t)__cvta_generic_to_shared(p);
}
__device__ __forceinline__ void cpa16(uint32_t saddr, const void* g) {
    asm volatile("cp.async.cg.shared.global [%0], [%1], 16;"
                 :: "r"(saddr), "l"(g));
}
#define CP_COMMIT() asm volatile("cp.async.commit_group;")
__device__ __forceinline__ void lds128(uint4& v, uint32_t addr) {
    asm volatile("ld.shared.v4.u32 {%0,%1,%2,%3}, [%4];"
                 : "=r"(v.x), "=r"(v.y), "=r"(v.z), "=r"(v.w) : "r"(addr));
}

#define APH 40     // attn smem pitch (halves)
#define AP2 72     // gemm A smem pitch (halves): 144B rows, conflict-free ldmatrix
#define ASTG2 18432   // A stage: 128 x 72 halves
#define BSTG2 16384   // B stage: fragment-packed chunk of 64 k
#define STAGE_BYTES (ASTG2 + BSTG2)   // 34816
#define NSTAGE 3
#define GEMM_SMEM  (NSTAGE * STAGE_BYTES)

// ---------------------------------------------------------------------------
// Kernel 0a: bias table
// ---------------------------------------------------------------------------
__global__ void bias_kernel(const float* __restrict__ rel1,
                            const float* __restrict__ rel2)
{
    int idx = blockIdx.x * blockDim.x + threadIdx.x;
    int s = idx >> 15, head = (idx >> 12) & 7, p = (idx >> 6) & 63, q = idx & 63;
    const float* rel = s ? rel2 : rel1;
    int a = (p >> 3) - (q >> 3) + 7;
    int b = (p & 7) - (q & 7) + 7;
    g_bias[idx] = rel[head * 225 + a * 15 + b];
}

// ---------------------------------------------------------------------------
// Kernel 0b: pack weights into fp16 fragment order (unchanged).
// ---------------------------------------------------------------------------
__global__ void wpack_kernel(const float* __restrict__ Wqkv1,
                             const float* __restrict__ Wqkv2,
                             const float* __restrict__ Wo1,
                             const float* __restrict__ Wo2)
{
    int idx = blockIdx.x * blockDim.x + threadIdx.x;   // 0..524287
    const float* W;
    int N, cb, r;
    if (idx < 393216) {
        int scb = idx >> 15;
        r = idx & 32767;
        int s = scb / 6; cb = scb % 6;
        W = s ? Wqkv2 : Wqkv1; N = 768;
    } else {
        int t = idx - 393216;
        int scb = t >> 15;
        r = t & 32767;
        int s = scb >> 1; cb = scb & 1;
        W = s ? Wo2 : Wo1; N = 256;
    }
    int c    = r >> 12;
    int r2   = r & 4095;
    int k16  = r2 >> 11;
    int r3   = r2 & 2047;
    int jp   = r3 >> 8;
    int r4   = r3 & 255;
    int lane = r4 >> 3;
    int e    = r4 & 7;
    int g = lane >> 2, t4 = lane & 3;
    int reg = e >> 1, h = e & 1;
    int k = c * 32 + k16 * 16 + ((reg & 1) ? 8 : 0) + 2 * t4 + h;
    int n = cb * 128 + jp * 16 + ((reg & 2) ? 8 : 0) + g;
    g_wh[idx] = __float2half_rn(W[k * N + n]);
}

// ---------------------------------------------------------------------------
// Kernel 0c: emb -> fp16 with fused roll + window gather ([s][R][k] rows)
// ---------------------------------------------------------------------------
__global__ __launch_bounds__(256)
void embh_kernel(const float* __restrict__ emb1, const float* __restrict__ emb2)
{
    unsigned idx = blockIdx.x * 256 + threadIdx.x;   // 8 halves each
    int s = idx >> 22;
    unsigned r = idx & 4194303u;
    unsigned R = r >> 5, gi = r & 31;
    int p_ = R & 63, win_ = (R >> 6) & 1023, b_ = R >> 16;
    int hs = (((win_ >> 5) << 3) + (p_ >> 3) + SHIFT) & 255;
    int ws = ((win_ & 31) << 3) + (p_ & 7);
    const float* src = (s ? emb2 : emb1)
                     + ((((size_t)b_ * HH + hs) * WW + ws) * CC) + gi * 8;
    float4 f0 = *reinterpret_cast<const float4*>(src);
    float4 f1 = *reinterpret_cast<const float4*>(src + 4);
    uint4 o;
    o.x = f22u(f0.x, f0.y); o.y = f22u(f0.z, f0.w);
    o.z = f22u(f1.x, f1.y); o.w = f22u(f1.z, f1.w);
    *reinterpret_cast<uint4*>(&g_embh[((size_t)s << 25) + (size_t)R * 256 + gi * 8]) = o;
}

// ---------------------------------------------------------------------------
// Kernel 1: QKV GEMM. Chunks of K=64 (4 chunks), 3-stage cp.async.
// __launch_bounds__(256,2) forces regs<=128 so 2 CTAs/SM stay resident.
// ---------------------------------------------------------------------------
__global__ __launch_bounds__(256, 2)
void qkv_mma(const float* __restrict__ bqkv1, const float* __restrict__ bqkv2)
{
    extern __shared__ __align__(16) __half sh[];
    const int s = blockIdx.z;
    const float* __restrict__ bq = s ? bqkv2 : bqkv1;
    const int colBlock = blockIdx.x;     // 0..5
    const int rowBlock = blockIdx.y;     // 0..1023
    const int tid  = threadIdx.x;
    const int wid  = tid >> 5;
    const int lane = tid & 31;
    const int g    = lane >> 2;
    const int t4   = lane & 3;
    const int lrow = lane & 7;

    const __half* aBase = g_embh + ((size_t)s << 25) + (size_t)rowBlock * 128 * 256;
    const __half* bBase = g_wh + (size_t)(s * 6 + colBlock) * 32768;

    const uint32_t smemBase = sm_a(sh);
    // A cp.async mapping: 1024 16B-units/chunk; unit = tid + i*256
    const int aR0 = tid >> 3, aJ0 = tid & 7;   // unit i computed inline to save regs

    const int wrb = (wid & 3) * 32;
    const int wq  = wid >> 2;
    const uint32_t aOff0 = ((wrb + lrow + ((lane >> 3) & 1) * 8) * AP2 + ((lane >> 4) & 1) * 8) * 2;
    const uint32_t aOff1 = aOff0 + 16 * AP2 * 2;
    const uint32_t bfOff = ASTG2 + ((wq * 4) * 32 + lane) * 16;   // +k16*4096 +jpLocal*512

#define QISSUE(c, st) do {                                                        \
    uint32_t ab = smemBase + (st) * STAGE_BYTES;                                  \
    uint32_t bb = ab + ASTG2;                                                     \
    cpa16(ab + (uint32_t)(aR0 * 9 + aJ0) * 16,            aBase + (aR0      ) * 256 + aJ0 * 8 + (c) * 64); \
    cpa16(ab + (uint32_t)((aR0 + 32) * 9 + aJ0) * 16,     aBase + (aR0 + 32 ) * 256 + aJ0 * 8 + (c) * 64); \
    cpa16(ab + (uint32_t)((aR0 + 64) * 9 + aJ0) * 16,     aBase + (aR0 + 64 ) * 256 + aJ0 * 8 + (c) * 64); \
    cpa16(ab + (uint32_t)((aR0 + 96) * 9 + aJ0) * 16,     aBase + (aR0 + 96 ) * 256 + aJ0 * 8 + (c) * 64); \
    cpa16(bb + (tid      ) * 16, bBase + (size_t)(c) * 8192 + (tid      ) * 8);   \
    cpa16(bb + (tid + 256) * 16, bBase + (size_t)(c) * 8192 + (tid + 256) * 8);   \
    cpa16(bb + (tid + 512) * 16, bBase + (size_t)(c) * 8192 + (tid + 512) * 8);   \
    cpa16(bb + (tid + 768) * 16, bBase + (size_t)(c) * 8192 + (tid + 768) * 8);   \
    CP_COMMIT();                                                                  \
} while (0)

    float acc[2][8][4];
#pragma unroll
    for (int mi = 0; mi < 2; mi++)
#pragma unroll
        for (int nj = 0; nj < 8; nj++)
#pragma unroll
            for (int k = 0; k < 4; k++) acc[mi][nj][k] = 0.f;

    QISSUE(0, 0);
    QISSUE(1, 1);

#pragma unroll
    for (int c = 0; c < 4; ++c) {
        const int st = c % NSTAGE;
        if (c < 3) asm volatile("cp.async.wait_group 1;");
        else       asm volatile("cp.async.wait_group 0;");
        __syncthreads();
        if (c < 2) QISSUE(c + 2, (c + 2) % NSTAGE);

        const uint32_t stb = smemBase + st * STAGE_BYTES;
#pragma unroll
        for (int k16 = 0; k16 < 4; ++k16) {
            uint4 bf[4];
#pragma unroll
            for (int jp = 0; jp < 4; ++jp)
                lds128(bf[jp], stb + bfOff + k16 * 4096 + jp * 512);
            uint32_t a0[2], a1[2], a2[2], a3[2];
            ldsm4(a0[0], a1[0], a2[0], a3[0], stb + aOff0 + k16 * 32);
            ldsm4(a0[1], a1[1], a2[1], a3[1], stb + aOff1 + k16 * 32);
#pragma unroll
            for (int jp = 0; jp < 4; ++jp) {
                const uint4 b = bf[jp];
                mma_f16(acc[0][2*jp],   a0[0], a1[0], a2[0], a3[0], b.x, b.y);
                mma_f16(acc[0][2*jp+1], a0[0], a1[0], a2[0], a3[0], b.z, b.w);
                mma_f16(acc[1][2*jp],   a0[1], a1[1], a2[1], a3[1], b.x, b.y);
                mma_f16(acc[1][2*jp+1], a0[1], a1[1], a2[1], a3[1], b.z, b.w);
            }
        }
    }
#undef QISSUE

    // Epilogue: add bias, convert fp16, scatter to q/k/v layout
    const int wcb = wq * 64;
#pragma unroll
    for (int mi = 0; mi < 2; mi++) {
#pragma unroll
        for (int h = 0; h < 2; h++) {
            int r  = rowBlock * 128 + wrb + mi * 16 + g + 8 * h;
            int pr = r & 63, wr = (r >> 6) & 1023, br = r >> 16;
#pragma unroll
            for (int nj = 0; nj < 8; nj++) {
                int n = colBlock * 128 + wcb + nj * 8 + t4 * 2;
                float vx = acc[mi][nj][h * 2 + 0] + bq[n];
                float vy = acc[mi][nj][h * 2 + 1] + bq[n + 1];
                int qkvi = n >> 8, head = (n >> 5) & 7, d = n & 31;
                size_t idx = ((((size_t)(s * 3 + qkvi) * BB + br) * NWIN + wr) * NH + head)
                                 * ((size_t)PP * HD)
                             + (size_t)pr * HD + d;
                __half2 hv = __floats2half2_rn(vx, vy);
                *reinterpret_cast<__half2*>(&g_qkvh[idx]) = hv;
            }
        }
    }
}

// ---------------------------------------------------------------------------
// Kernel 2: windowed cross-attention, register softmax + ldmatrix (unchanged).
// ---------------------------------------------------------------------------
__global__ __launch_bounds__(128)
void attn_mma()
{
    const int s    = blockIdx.z;
    const int head = blockIdx.y;
    const int bw   = blockIdx.x;
    const int b    = bw >> 10;
    const int win  = bw & 1023;
    const int os   = 1 - s;

    __shared__ __align__(16) __half qs[64 * APH];
    __shared__ __align__(16) __half ks[64 * APH];
    __shared__ __align__(16) __half vs[64 * APH];   // [p][d]

    const int tid = threadIdx.x;
    const size_t tile = (size_t)PP * HD;
    const size_t qbase = (((((size_t)s  * 3 + 0) * BB + b) * NWIN + win) * NH + head) * tile;
    const size_t kbase = (((((size_t)os * 3 + 1) * BB + b) * NWIN + win) * NH + head) * tile;
    const size_t vbase = (((((size_t)os * 3 + 2) * BB + b) * NWIN + win) * NH + head) * tile;

    {
        const uint4* qg = reinterpret_cast<const uint4*>(&g_qkvh[qbase]);
        const uint4* kg = reinterpret_cast<const uint4*>(&g_qkvh[kbase]);
        const uint4* vg = reinterpret_cast<const uint4*>(&g_qkvh[vbase]);
        int u  = tid * 2;
        int p  = tid >> 1;
        int d0 = (tid & 1) * 16;
        uint4 x0 = qg[u], x1 = qg[u + 1];
        *reinterpret_cast<uint4*>(&qs[p * APH + d0])     = x0;
        *reinterpret_cast<uint4*>(&qs[p * APH + d0 + 8]) = x1;
        uint4 y0 = kg[u], y1 = kg[u + 1];
        *reinterpret_cast<uint4*>(&ks[p * APH + d0])     = y0;
        *reinterpret_cast<uint4*>(&ks[p * APH + d0 + 8]) = y1;
        uint4 z0 = vg[u], z1 = vg[u + 1];
        *reinterpret_cast<uint4*>(&vs[p * APH + d0])     = z0;
        *reinterpret_cast<uint4*>(&vs[p * APH + d0 + 8]) = z1;
    }
    __syncthreads();

    const int w    = tid >> 5;
    const int lane = tid & 31;
    const int g    = lane >> 2;
    const int t4   = lane & 3;
    const int r0   = w * 16;
    const int lrow = lane & 7;

    uint32_t qAddr = sm_a(&qs[(r0 + lrow + ((lane >> 3) & 1) * 8) * APH + ((lane >> 4) & 1) * 8]);
    uint32_t kAddr = sm_a(&ks[(lrow + ((lane >> 4) & 1) * 8) * APH + ((lane >> 3) & 1) * 8]);
    uint32_t vAddr = sm_a(&vs[(lrow + ((lane >> 3) & 1) * 8) * APH + ((lane >> 4) & 1) * 8]);

    float c1[8][4];
#pragma unroll
    for (int nj = 0; nj < 8; nj++)
#pragma unroll
        for (int k = 0; k < 4; k++) c1[nj][k] = 0.f;

#pragma unroll
    for (int k16 = 0; k16 < 2; ++k16) {
        uint32_t a0, a1, a2, a3;
        ldsm4(a0, a1, a2, a3, qAddr + k16 * 32);
#pragma unroll
        for (int jp = 0; jp < 4; ++jp) {
            uint32_t b00, b10, b01, b11;
            ldsm4(b00, b10, b01, b11, kAddr + jp * (16 * APH * 2) + k16 * 32);
            mma_f16(c1[2*jp],   a0, a1, a2, a3, b00, b10);
            mma_f16(c1[2*jp+1], a0, a1, a2, a3, b01, b11);
        }
    }

    const size_t bbias = ((size_t)s * NH + head) * 4096;
    const bool mh = ((win >> 5) == 31);
    const bool mw = ((win & 31) == 31);
    const float scale = 0.17677669529663687f;
    const int rowA = r0 + g, rowB = rowA + 8;
    const int ipA = rowA >> 3, jpA = rowA & 7;
    const int ipB = rowB >> 3, jpB = rowB & 7;
    const int jq0 = 2 * t4, jq1 = 2 * t4 + 1;

    float mA = -1e30f, mB = -1e30f;
#pragma unroll
    for (int nj = 0; nj < 8; nj++) {
        int col = nj * 8 + 2 * t4;
        int iq  = col >> 3;
        float2 bA = *reinterpret_cast<const float2*>(&g_bias[bbias + rowA * 64 + col]);
        float2 bB = *reinterpret_cast<const float2*>(&g_bias[bbias + rowB * 64 + col]);
        bool hA = mh && ((ipA < 4) != (iq < 4));
        bool hB = mh && ((ipB < 4) != (iq < 4));
        bool w0A = hA || (mw && ((jpA < 4) != (jq0 < 4)));
        bool w1A = hA || (mw && ((jpA < 4) != (jq1 < 4)));
        bool w0B = hB || (mw && ((jpB < 4) != (jq0 < 4)));
        bool w1B = hB || (mw && ((jpB < 4) != (jq1 < 4)));
        float v0 = w0A ? -1e30f : c1[nj][0] * scale + bA.x;
        float v1 = w1A ? -1e30f : c1[nj][1] * scale + bA.y;
        float v2 = w0B ? -1e30f : c1[nj][2] * scale + bB.x;
        float v3 = w1B ? -1e30f : c1[nj][3] * scale + bB.y;
        c1[nj][0] = v0; c1[nj][1] = v1; c1[nj][2] = v2; c1[nj][3] = v3;
        mA = fmaxf(mA, fmaxf(v0, v1));
        mB = fmaxf(mB, fmaxf(v2, v3));
    }
    mA = fmaxf(mA, __shfl_xor_sync(0xffffffffu, mA, 1));
    mA = fmaxf(mA, __shfl_xor_sync(0xffffffffu, mA, 2));
    mB = fmaxf(mB, __shfl_xor_sync(0xffffffffu, mB, 1));
    mB = fmaxf(mB, __shfl_xor_sync(0xffffffffu, mB, 2));

    float sA = 0.f, sB = 0.f;
#pragma unroll
    for (int nj = 0; nj < 8; nj++) {
        float e0 = __expf(c1[nj][0] - mA);
        float e1 = __expf(c1[nj][1] - mA);
        float e2 = __expf(c1[nj][2] - mB);
        float e3 = __expf(c1[nj][3] - mB);
        c1[nj][0] = e0; c1[nj][1] = e1; c1[nj][2] = e2; c1[nj][3] = e3;
        sA += e0 + e1; sB += e2 + e3;
    }
    sA += __shfl_xor_sync(0xffffffffu, sA, 1);
    sA += __shfl_xor_sync(0xffffffffu, sA, 2);
    sB += __shfl_xor_sync(0xffffffffu, sB, 1);
    sB += __shfl_xor_sync(0xffffffffu, sB, 2);
    const float invA = 1.f / sA, invB = 1.f / sB;

    float c2[4][4];
#pragma unroll
    for (int nj = 0; nj < 4; nj++)
#pragma unroll
        for (int k = 0; k < 4; k++) c2[nj][k] = 0.f;

#pragma unroll
    for (int k16 = 0; k16 < 4; ++k16) {
        uint32_t a0 = f22u(c1[2*k16][0]   * invA, c1[2*k16][1]   * invA);
        uint32_t a1 = f22u(c1[2*k16][2]   * invB, c1[2*k16][3]   * invB);
        uint32_t a2 = f22u(c1[2*k16+1][0] * invA, c1[2*k16+1][1] * invA);
        uint32_t a3 = f22u(c1[2*k16+1][2] * invB, c1[2*k16+1][3] * invB);
#pragma unroll
        for (int jp = 0; jp < 2; ++jp) {
            uint32_t b00, b10, b01, b11;
            ldsm4t(b00, b10, b01, b11, vAddr + k16 * (16 * APH * 2) + jp * 32);
            mma_f16(c2[2*jp],   a0, a1, a2, a3, b00, b10);
            mma_f16(c2[2*jp+1], a0, a1, a2, a3, b01, b11);
        }
    }

    const size_t obase = (size_t)s * ((size_t)BB * NWIN * PP * CC)
                       + (((size_t)b * NWIN + win) * PP) * CC
                       + (size_t)head * HD;
#pragma unroll
    for (int nj = 0; nj < 4; nj++) {
#pragma unroll
        for (int h2 = 0; h2 < 2; h2++) {
            int row = r0 + g + 8 * h2;
            int col = nj * 8 + t4 * 2;
            __half2 hv = __floats2half2_rn(c2[nj][h2 * 2 + 0], c2[nj][h2 * 2 + 1]);
            *reinterpret_cast<__half2*>(&g_attnh[obase + (size_t)row * CC + col]) = hv;
        }
    }
}

// ---------------------------------------------------------------------------
// Kernel 3: output projection. Chunk-64, launch_bounds(256,2).
// ---------------------------------------------------------------------------
__global__ __launch_bounds__(256, 2)
void proj_mma(const float* __restrict__ bo1, const float* __restrict__ bo2,
              float* __restrict__ out)
{
    extern __shared__ __align__(16) __half sh[];
    const int s = blockIdx.z;
    const float* __restrict__ bo = s ? bo2 : bo1;
    float* __restrict__ dst = out + (size_t)s * ((size_t)BB * HH * WW * OUTC);
    const int colBlock = blockIdx.x;     // 0..1
    const int rowBlock = blockIdx.y;     // 0..1023
    const int tid  = threadIdx.x;
    const int wid  = tid >> 5;
    const int lane = tid & 31;
    const int g    = lane >> 2;
    const int t4   = lane & 3;
    const int lrow = lane & 7;

    const __half* aBase = g_attnh + (size_t)s * ((size_t)BB * NWIN * PP * CC)
                        + (size_t)rowBlock * 128 * 256;
    const __half* bBase = g_wh + 393216 + (size_t)(s * 2 + colBlock) * 32768;

    const uint32_t smemBase = sm_a(sh);
    const int aR0 = tid >> 3, aJ0 = tid & 7;

    const int wrb = (wid & 3) * 32;
    const int wq  = wid >> 2;
    const uint32_t aOff0 = ((wrb + lrow + ((lane >> 3) & 1) * 8) * AP2 + ((lane >> 4) & 1) * 8) * 2;
    const uint32_t aOff1 = aOff0 + 16 * AP2 * 2;
    const uint32_t bfOff = ASTG2 + ((wq * 4) * 32 + lane) * 16;

#define PISSUE(c, st) do {                                                        \
    uint32_t ab = smemBase + (st) * STAGE_BYTES;                                  \
    uint32_t bb = ab + ASTG2;                                                     \
    cpa16(ab + (uint32_t)(aR0 * 9 + aJ0) * 16,        aBase + (aR0      ) * 256 + aJ0 * 8 + (c) * 64); \
    cpa16(ab + (uint32_t)((aR0 + 32) * 9 + aJ0) * 16, aBase + (aR0 + 32 ) * 256 + aJ0 * 8 + (c) * 64); \
    cpa16(ab + (uint32_t)((aR0 + 64) * 9 + aJ0) * 16, aBase + (aR0 + 64 ) * 256 + aJ0 * 8 + (c) * 64); \
    cpa16(ab + (uint32_t)((aR0 + 96) * 9 + aJ0) * 16, aBase + (aR0 + 96 ) * 256 + aJ0 * 8 + (c) * 64); \
    cpa16(bb + (tid      ) * 16, bBase + (size_t)(c) * 8192 + (tid      ) * 8);   \
    cpa16(bb + (tid + 256) * 16, bBase + (size_t)(c) * 8192 + (tid + 256) * 8);   \
    cpa16(bb + (tid + 512) * 16, bBase + (size_t)(c) * 8192 + (tid + 512) * 8);   \
    cpa16(bb + (tid + 768) * 16, bBase + (size_t)(c) * 8192 + (tid + 768) * 8);   \
    CP_COMMIT();                                                                  \
} while (0)

    float acc[2][8][4];
#pragma unroll
    for (int mi = 0; mi < 2; mi++)
#pragma unroll
        for (int nj = 0; nj < 8; nj++)
#pragma unroll
            for (int k = 0; k < 4; k++) acc[mi][nj][k] = 0.f;

    PISSUE(0, 0);
    PISSUE(1, 1);

#pragma unroll
    for (int c = 0; c < 4; ++c) {
        const int st = c % NSTAGE;
        if (c < 3) asm volatile("cp.async.wait_group 1;");
        else       asm volatile("cp.async.wait_group 0;");
        __syncthreads();
        if (c < 2) PISSUE(c + 2, (c + 2) % NSTAGE);

        const uint32_t stb = smemBase + st * STAGE_BYTES;
#pragma unroll
        for (int k16 = 0; k16 < 4; ++k16) {
            uint4 bf[4];
#pragma unroll
            for (int jp = 0; jp < 4; ++jp)
                lds128(bf[jp], stb + bfOff + k16 * 4096 + jp * 512);
            uint32_t a0[2], a1[2], a2[2], a3[2];
            ldsm4(a0[0], a1[0], a2[0], a3[0], stb + aOff0 + k16 * 32);
            ldsm4(a0[1], a1[1], a2[1], a3[1], stb + aOff1 + k16 * 32);
#pragma unroll
            for (int jp = 0; jp < 4; ++jp) {
                const uint4 b = bf[jp];
                mma_f16(acc[0][2*jp],   a0[0], a1[0], a2[0], a3[0], b.x, b.y);
                mma_f16(acc[0][2*jp+1], a0[0], a1[0], a2[0], a3[0], b.z, b.w);
                mma_f16(acc[1][2*jp],   a0[1], a1[1], a2[1], a3[1], b.x, b.y);
                mma_f16(acc[1][2*jp+1], a0[1], a1[1], a2[1], a3[1], b.z, b.w);
            }
        }
    }
#undef PISSUE

    // Epilogue: unwindow + roll scatter (fp32 output)
    const int wcb = wq * 64;
#pragma unroll
    for (int mi = 0; mi < 2; mi++) {
#pragma unroll
        for (int h = 0; h < 2; h++) {
            int r  = rowBlock * 128 + wrb + mi * 16 + g + 8 * h;
            int pr = r & 63, wr = (r >> 6) & 1023, br = r >> 16;
            int hout = (((wr >> 5) << 3) + (pr >> 3) + SHIFT) & 255;
            int wout = ((wr & 31) << 3) + (pr & 7);
            size_t rowbase = (((size_t)br * HH + hout) * WW + wout) * OUTC;
#pragma unroll
            for (int nj = 0; nj < 8; nj++) {
                int n = colBlock * 128 + wcb + nj * 8 + t4 * 2;
                float2 v;
                v.x = acc[mi][nj][h * 2 + 0] + bo[n];
                v.y = acc[mi][nj][h * 2 + 1] + bo[n + 1];
                *reinterpret_cast<float2*>(&dst[rowbase + n]) = v;
            }
        }
    }
}

// ---------------------------------------------------------------------------
// Launch
// ---------------------------------------------------------------------------
extern "C" void kernel_launch(void* const* d_in, const int* in_sizes, int n_in,
                              void* d_out, int out_size)
{
    const float* emb1  = (const float*)d_in[0];
    const float* emb2  = (const float*)d_in[1];
    const float* Wqkv1 = (const float*)d_in[2];
    const float* bqkv1 = (const float*)d_in[3];
    const float* Wqkv2 = (const float*)d_in[4];
    const float* bqkv2 = (const float*)d_in[5];
    const float* rel1  = (const float*)d_in[6];
    const float* rel2  = (const float*)d_in[7];
    const float* Wo1   = (const float*)d_in[8];
    const float* bo1   = (const float*)d_in[9];
    const float* Wo2   = (const float*)d_in[10];
    const float* bo2   = (const float*)d_in[11];
    float* out = (float*)d_out;
    (void)in_sizes; (void)n_in; (void)out_size;

    cudaFuncSetAttribute(qkv_mma,  cudaFuncAttributeMaxDynamicSharedMemorySize, GEMM_SMEM);
    cudaFuncSetAttribute(proj_mma, cudaFuncAttributeMaxDynamicSharedMemorySize, GEMM_SMEM);

    bias_kernel<<<256, 256>>>(rel1, rel2);
    wpack_kernel<<<2048, 256>>>(Wqkv1, Wqkv2, Wo1, Wo2);
    embh_kernel<<<32768, 256>>>(emb1, emb2);

    dim3 gq(6, 1024, 2);
    qkv_mma<<<gq, 256, GEMM_SMEM>>>(bqkv1, bqkv2);

    dim3 ga(2048, 8, 2);
    attn_mma<<<ga, 128>>>();

    dim3 gp(2, 1024, 2);
    proj_mma<<<gp, 256, GEMM_SMEM>>>(bo1, bo2, out);
}

// round 17
// speedup vs baseline: 1.1929x; 1.0424x over previous
#include <cuda_runtime.h>
#include <cuda_fp16.h>
#include <cstdint>

// Problem constants
#define BB 2
#define HH 256
#define WW 256
#define CC 256
#define WS 8
#define SHIFT 4
#define NH 8
#define HD 32
#define OUTC 256
#define NWIN 1024
#define PP 64
#define MROWS 131072

// Scratch (device globals)
__device__ __half g_embh[2u*131072u*256u];          // rolled+windowed emb, fp16 [s][R][k]
__device__ __half g_qkvh[2u*3u*BB*NWIN*NH*PP*HD];   // [s][qkv][b][win][head][p][d] fp16
__device__ __half g_attnh[2u*BB*NWIN*PP*CC];        // [s][b][win][p][C] fp16
// Bias table in fp16 FRAGMENT order: [s][head][w(4)][lane(32)][e(32)]
//   e = nj*4 + h2*2 + j ; value = bias[w*16+(lane>>2)+8*h2][nj*8+(lane&3)*2+j]
__device__ __half g_biash[2*NH*4*32*32];
// Weights packed in per-lane FRAGMENT order:
//   per (s,cb): [c][k16][jp(8)][lane(32)] x uint4{b00,b10,b01,b11}
__device__ __half g_wh[524288];

__device__ __forceinline__ uint32_t f22u(float a, float b) {
    __half2 h = __floats2half2_rn(a, b);
    return *reinterpret_cast<uint32_t*>(&h);
}

__device__ __forceinline__ void mma_f16(float c[4],
                                        uint32_t a0, uint32_t a1, uint32_t a2, uint32_t a3,
                                        uint32_t b0, uint32_t b1) {
    asm volatile(
        "mma.sync.aligned.m16n8k16.row.col.f32.f16.f16.f32 "
        "{%0,%1,%2,%3}, {%4,%5,%6,%7}, {%8,%9}, {%0,%1,%2,%3};"
        : "+f"(c[0]), "+f"(c[1]), "+f"(c[2]), "+f"(c[3])
        : "r"(a0), "r"(a1), "r"(a2), "r"(a3), "r"(b0), "r"(b1));
}

__device__ __forceinline__ void ldsm4(uint32_t& r0, uint32_t& r1, uint32_t& r2, uint32_t& r3,
                                      uint32_t addr) {
    asm volatile("ldmatrix.sync.aligned.m8n8.x4.shared.b16 {%0,%1,%2,%3}, [%4];"
                 : "=r"(r0), "=r"(r1), "=r"(r2), "=r"(r3) : "r"(addr));
}
__device__ __forceinline__ void ldsm4t(uint32_t& r0, uint32_t& r1, uint32_t& r2, uint32_t& r3,
                                       uint32_t addr) {
    asm volatile("ldmatrix.sync.aligned.m8n8.x4.trans.shared.b16 {%0,%1,%2,%3}, [%4];"
                 : "=r"(r0), "=r"(r1), "=r"(r2), "=r"(r3) : "r"(addr));
}
__device__ __forceinline__ uint32_t sm_a(const void* p) {
    return (uint32_t)__cvta_generic_to_shared(p);
}
__device__ __forceinline__ void cpa16(uint32_t saddr, const void* g) {
    asm volatile("cp.async.cg.shared.global [%0], [%1], 16;"
                 :: "r"(saddr), "l"(g));
}
#define CP_COMMIT() asm volatile("cp.async.commit_group;")
__device__ __forceinline__ void lds128(uint4& v, uint32_t addr) {
    asm volatile("ld.shared.v4.u32 {%0,%1,%2,%3}, [%4];"
                 : "=r"(v.x), "=r"(v.y), "=r"(v.z), "=r"(v.w) : "r"(addr));
}

#define APH 40     // attn smem pitch (halves)
#define AP2 72     // gemm A smem pitch (halves): 144B rows, conflict-free ldmatrix
#define ASTG2 18432   // A stage: 128 x 72 halves
#define BSTG2 16384   // B stage: fragment-packed chunk of 64 k
#define STAGE_BYTES (ASTG2 + BSTG2)   // 34816
#define NSTAGE 3
#define GEMM_SMEM  (NSTAGE * STAGE_BYTES)

// ---------------------------------------------------------------------------
// Kernel 0a: bias table, fp16 fragment order
// ---------------------------------------------------------------------------
__global__ void bias_kernel(const float* __restrict__ rel1,
                            const float* __restrict__ rel2)
{
    int idx = blockIdx.x * blockDim.x + threadIdx.x;   // 0..65535
    int s    = idx >> 15;
    int head = (idx >> 12) & 7;
    int w    = (idx >> 10) & 3;
    int lane = (idx >> 5) & 31;
    int e    = idx & 31;
    int nj = e >> 2, h2 = (e >> 1) & 1, j = e & 1;
    int row = w * 16 + (lane >> 2) + 8 * h2;
    int col = nj * 8 + (lane & 3) * 2 + j;
    const float* rel = s ? rel2 : rel1;
    int a = (row >> 3) - (col >> 3) + 7;
    int b = (row & 7) - (col & 7) + 7;
    g_biash[idx] = __float2half_rn(rel[head * 225 + a * 15 + b]);
}

// ---------------------------------------------------------------------------
// Kernel 0b: pack weights into fp16 fragment order (unchanged).
// ---------------------------------------------------------------------------
__global__ void wpack_kernel(const float* __restrict__ Wqkv1,
                             const float* __restrict__ Wqkv2,
                             const float* __restrict__ Wo1,
                             const float* __restrict__ Wo2)
{
    int idx = blockIdx.x * blockDim.x + threadIdx.x;   // 0..524287
    const float* W;
    int N, cb, r;
    if (idx < 393216) {
        int scb = idx >> 15;
        r = idx & 32767;
        int s = scb / 6; cb = scb % 6;
        W = s ? Wqkv2 : Wqkv1; N = 768;
    } else {
        int t = idx - 393216;
        int scb = t >> 15;
        r = t & 32767;
        int s = scb >> 1; cb = scb & 1;
        W = s ? Wo2 : Wo1; N = 256;
    }
    int c    = r >> 12;
    int r2   = r & 4095;
    int k16  = r2 >> 11;
    int r3   = r2 & 2047;
    int jp   = r3 >> 8;
    int r4   = r3 & 255;
    int lane = r4 >> 3;
    int e    = r4 & 7;
    int g = lane >> 2, t4 = lane & 3;
    int reg = e >> 1, h = e & 1;
    int k = c * 32 + k16 * 16 + ((reg & 1) ? 8 : 0) + 2 * t4 + h;
    int n = cb * 128 + jp * 16 + ((reg & 2) ? 8 : 0) + g;
    g_wh[idx] = __float2half_rn(W[k * N + n]);
}

// ---------------------------------------------------------------------------
// Kernel 0c: emb -> fp16 with fused roll + window gather ([s][R][k] rows)
// ---------------------------------------------------------------------------
__global__ __launch_bounds__(256)
void embh_kernel(const float* __restrict__ emb1, const float* __restrict__ emb2)
{
    unsigned idx = blockIdx.x * 256 + threadIdx.x;   // 8 halves each
    int s = idx >> 22;
    unsigned r = idx & 4194303u;
    unsigned R = r >> 5, gi = r & 31;
    int p_ = R & 63, win_ = (R >> 6) & 1023, b_ = R >> 16;
    int hs = (((win_ >> 5) << 3) + (p_ >> 3) + SHIFT) & 255;
    int ws = ((win_ & 31) << 3) + (p_ & 7);
    const float* src = (s ? emb2 : emb1)
                     + ((((size_t)b_ * HH + hs) * WW + ws) * CC) + gi * 8;
    float4 f0 = *reinterpret_cast<const float4*>(src);
    float4 f1 = *reinterpret_cast<const float4*>(src + 4);
    uint4 o;
    o.x = f22u(f0.x, f0.y); o.y = f22u(f0.z, f0.w);
    o.z = f22u(f1.x, f1.y); o.w = f22u(f1.z, f1.w);
    *reinterpret_cast<uint4*>(&g_embh[((size_t)s << 25) + (size_t)R * 256 + gi * 8]) = o;
}

// ---------------------------------------------------------------------------
// Kernel 1: QKV GEMM. Chunks of K=64 (4 chunks), 3-stage cp.async.
// __launch_bounds__(256,2) forces regs<=128 so 2 CTAs/SM stay resident.
// ---------------------------------------------------------------------------
__global__ __launch_bounds__(256, 2)
void qkv_mma(const float* __restrict__ bqkv1, const float* __restrict__ bqkv2)
{
    extern __shared__ __align__(16) __half sh[];
    const int s = blockIdx.z;
    const float* __restrict__ bq = s ? bqkv2 : bqkv1;
    const int colBlock = blockIdx.x;     // 0..5
    const int rowBlock = blockIdx.y;     // 0..1023
    const int tid  = threadIdx.x;
    const int wid  = tid >> 5;
    const int lane = tid & 31;
    const int g    = lane >> 2;
    const int t4   = lane & 3;
    const int lrow = lane & 7;

    const __half* aBase = g_embh + ((size_t)s << 25) + (size_t)rowBlock * 128 * 256;
    const __half* bBase = g_wh + (size_t)(s * 6 + colBlock) * 32768;

    const uint32_t smemBase = sm_a(sh);
    const int aR0 = tid >> 3, aJ0 = tid & 7;

    const int wrb = (wid & 3) * 32;
    const int wq  = wid >> 2;
    const uint32_t aOff0 = ((wrb + lrow + ((lane >> 3) & 1) * 8) * AP2 + ((lane >> 4) & 1) * 8) * 2;
    const uint32_t aOff1 = aOff0 + 16 * AP2 * 2;
    const uint32_t bfOff = ASTG2 + ((wq * 4) * 32 + lane) * 16;

#define QISSUE(c, st) do {                                                        \
    uint32_t ab = smemBase + (st) * STAGE_BYTES;                                  \
    uint32_t bb = ab + ASTG2;                                                     \
    cpa16(ab + (uint32_t)(aR0 * 9 + aJ0) * 16,            aBase + (aR0      ) * 256 + aJ0 * 8 + (c) * 64); \
    cpa16(ab + (uint32_t)((aR0 + 32) * 9 + aJ0) * 16,     aBase + (aR0 + 32 ) * 256 + aJ0 * 8 + (c) * 64); \
    cpa16(ab + (uint32_t)((aR0 + 64) * 9 + aJ0) * 16,     aBase + (aR0 + 64 ) * 256 + aJ0 * 8 + (c) * 64); \
    cpa16(ab + (uint32_t)((aR0 + 96) * 9 + aJ0) * 16,     aBase + (aR0 + 96 ) * 256 + aJ0 * 8 + (c) * 64); \
    cpa16(bb + (tid      ) * 16, bBase + (size_t)(c) * 8192 + (tid      ) * 8);   \
    cpa16(bb + (tid + 256) * 16, bBase + (size_t)(c) * 8192 + (tid + 256) * 8);   \
    cpa16(bb + (tid + 512) * 16, bBase + (size_t)(c) * 8192 + (tid + 512) * 8);   \
    cpa16(bb + (tid + 768) * 16, bBase + (size_t)(c) * 8192 + (tid + 768) * 8);   \
    CP_COMMIT();                                                                  \
} while (0)

    float acc[2][8][4];
#pragma unroll
    for (int mi = 0; mi < 2; mi++)
#pragma unroll
        for (int nj = 0; nj < 8; nj++)
#pragma unroll
            for (int k = 0; k < 4; k++) acc[mi][nj][k] = 0.f;

    QISSUE(0, 0);
    QISSUE(1, 1);

#pragma unroll
    for (int c = 0; c < 4; ++c) {
        const int st = c % NSTAGE;
        if (c < 3) asm volatile("cp.async.wait_group 1;");
        else       asm volatile("cp.async.wait_group 0;");
        __syncthreads();
        if (c < 2) QISSUE(c + 2, (c + 2) % NSTAGE);

        const uint32_t stb = smemBase + st * STAGE_BYTES;
#pragma unroll
        for (int k16 = 0; k16 < 4; ++k16) {
            uint4 bf[4];
#pragma unroll
            for (int jp = 0; jp < 4; ++jp)
                lds128(bf[jp], stb + bfOff + k16 * 4096 + jp * 512);
            uint32_t a0[2], a1[2], a2[2], a3[2];
            ldsm4(a0[0], a1[0], a2[0], a3[0], stb + aOff0 + k16 * 32);
            ldsm4(a0[1], a1[1], a2[1], a3[1], stb + aOff1 + k16 * 32);
#pragma unroll
            for (int jp = 0; jp < 4; ++jp) {
                const uint4 b = bf[jp];
                mma_f16(acc[0][2*jp],   a0[0], a1[0], a2[0], a3[0], b.x, b.y);
                mma_f16(acc[0][2*jp+1], a0[0], a1[0], a2[0], a3[0], b.z, b.w);
                mma_f16(acc[1][2*jp],   a0[1], a1[1], a2[1], a3[1], b.x, b.y);
                mma_f16(acc[1][2*jp+1], a0[1], a1[1], a2[1], a3[1], b.z, b.w);
            }
        }
    }
#undef QISSUE

    // Epilogue: add bias, convert fp16, scatter to q/k/v layout
    const int wcb = wq * 64;
#pragma unroll
    for (int mi = 0; mi < 2; mi++) {
#pragma unroll
        for (int h = 0; h < 2; h++) {
            int r  = rowBlock * 128 + wrb + mi * 16 + g + 8 * h;
            int pr = r & 63, wr = (r >> 6) & 1023, br = r >> 16;
#pragma unroll
            for (int nj = 0; nj < 8; nj++) {
                int n = colBlock * 128 + wcb + nj * 8 + t4 * 2;
                float vx = acc[mi][nj][h * 2 + 0] + bq[n];
                float vy = acc[mi][nj][h * 2 + 1] + bq[n + 1];
                int qkvi = n >> 8, head = (n >> 5) & 7, d = n & 31;
                size_t idx = ((((size_t)(s * 3 + qkvi) * BB + br) * NWIN + wr) * NH + head)
                                 * ((size_t)PP * HD)
                             + (size_t)pr * HD + d;
                __half2 hv = __floats2half2_rn(vx, vy);
                *reinterpret_cast<__half2*>(&g_qkvh[idx]) = hv;
            }
        }
    }
}

// ---------------------------------------------------------------------------
// Kernel 2: windowed cross-attention, register softmax + ldmatrix.
// Bias loaded as 4x LDG.128 in fragment order.
// ---------------------------------------------------------------------------
__global__ __launch_bounds__(128)
void attn_mma()
{
    const int s    = blockIdx.z;
    const int head = blockIdx.y;
    const int bw   = blockIdx.x;
    const int b    = bw >> 10;
    const int win  = bw & 1023;
    const int os   = 1 - s;

    __shared__ __align__(16) __half qs[64 * APH];
    __shared__ __align__(16) __half ks[64 * APH];
    __shared__ __align__(16) __half vs[64 * APH];   // [p][d]

    const int tid = threadIdx.x;
    const size_t tile = (size_t)PP * HD;
    const size_t qbase = (((((size_t)s  * 3 + 0) * BB + b) * NWIN + win) * NH + head) * tile;
    const size_t kbase = (((((size_t)os * 3 + 1) * BB + b) * NWIN + win) * NH + head) * tile;
    const size_t vbase = (((((size_t)os * 3 + 2) * BB + b) * NWIN + win) * NH + head) * tile;

    {
        const uint4* qg = reinterpret_cast<const uint4*>(&g_qkvh[qbase]);
        const uint4* kg = reinterpret_cast<const uint4*>(&g_qkvh[kbase]);
        const uint4* vg = reinterpret_cast<const uint4*>(&g_qkvh[vbase]);
        int u  = tid * 2;
        int p  = tid >> 1;
        int d0 = (tid & 1) * 16;
        uint4 x0 = qg[u], x1 = qg[u + 1];
        *reinterpret_cast<uint4*>(&qs[p * APH + d0])     = x0;
        *reinterpret_cast<uint4*>(&qs[p * APH + d0 + 8]) = x1;
        uint4 y0 = kg[u], y1 = kg[u + 1];
        *reinterpret_cast<uint4*>(&ks[p * APH + d0])     = y0;
        *reinterpret_cast<uint4*>(&ks[p * APH + d0 + 8]) = y1;
        uint4 z0 = vg[u], z1 = vg[u + 1];
        *reinterpret_cast<uint4*>(&vs[p * APH + d0])     = z0;
        *reinterpret_cast<uint4*>(&vs[p * APH + d0 + 8]) = z1;
    }

    const int w    = tid >> 5;
    const int lane = tid & 31;
    const int g    = lane >> 2;
    const int t4   = lane & 3;
    const int r0   = w * 16;
    const int lrow = lane & 7;

    // Bias: 32 halves per thread, fragment order -> 4 LDG.128 (issued pre-sync)
    uint4 bias4[4];
    {
        const uint4* bp = reinterpret_cast<const uint4*>(
            g_biash + ((((size_t)s * NH + head) * 4 + w) * 32 + lane) * 32);
        bias4[0] = bp[0]; bias4[1] = bp[1]; bias4[2] = bp[2]; bias4[3] = bp[3];
    }
    __syncthreads();

    uint32_t qAddr = sm_a(&qs[(r0 + lrow + ((lane >> 3) & 1) * 8) * APH + ((lane >> 4) & 1) * 8]);
    uint32_t kAddr = sm_a(&ks[(lrow + ((lane >> 4) & 1) * 8) * APH + ((lane >> 3) & 1) * 8]);
    uint32_t vAddr = sm_a(&vs[(lrow + ((lane >> 3) & 1) * 8) * APH + ((lane >> 4) & 1) * 8]);

    float c1[8][4];
#pragma unroll
    for (int nj = 0; nj < 8; nj++)
#pragma unroll
        for (int k = 0; k < 4; k++) c1[nj][k] = 0.f;

#pragma unroll
    for (int k16 = 0; k16 < 2; ++k16) {
        uint32_t a0, a1, a2, a3;
        ldsm4(a0, a1, a2, a3, qAddr + k16 * 32);
#pragma unroll
        for (int jp = 0; jp < 4; ++jp) {
            uint32_t b00, b10, b01, b11;
            ldsm4(b00, b10, b01, b11, kAddr + jp * (16 * APH * 2) + k16 * 32);
            mma_f16(c1[2*jp],   a0, a1, a2, a3, b00, b10);
            mma_f16(c1[2*jp+1], a0, a1, a2, a3, b01, b11);
        }
    }

    const bool mh = ((win >> 5) == 31);
    const bool mw = ((win & 31) == 31);
    const float scale = 0.17677669529663687f;
    const int rowA = r0 + g, rowB = rowA + 8;
    const int ipA = rowA >> 3, jpA = rowA & 7;
    const int ipB = rowB >> 3, jpB = rowB & 7;
    const int jq0 = 2 * t4, jq1 = 2 * t4 + 1;
    const uint32_t* bu = reinterpret_cast<const uint32_t*>(bias4);

    float mA = -1e30f, mB = -1e30f;
#pragma unroll
    for (int nj = 0; nj < 8; nj++) {
        int col = nj * 8 + 2 * t4;
        int iq  = col >> 3;
        float2 bA = __half22float2(*reinterpret_cast<const __half2*>(&bu[nj * 2 + 0]));
        float2 bB = __half22float2(*reinterpret_cast<const __half2*>(&bu[nj * 2 + 1]));
        bool hA = mh && ((ipA < 4) != (iq < 4));
        bool hB = mh && ((ipB < 4) != (iq < 4));
        bool w0A = hA || (mw && ((jpA < 4) != (jq0 < 4)));
        bool w1A = hA || (mw && ((jpA < 4) != (jq1 < 4)));
        bool w0B = hB || (mw && ((jpB < 4) != (jq0 < 4)));
        bool w1B = hB || (mw && ((jpB < 4) != (jq1 < 4)));
        float v0 = w0A ? -1e30f : c1[nj][0] * scale + bA.x;
        float v1 = w1A ? -1e30f : c1[nj][1] * scale + bA.y;
        float v2 = w0B ? -1e30f : c1[nj][2] * scale + bB.x;
        float v3 = w1B ? -1e30f : c1[nj][3] * scale + bB.y;
        c1[nj][0] = v0; c1[nj][1] = v1; c1[nj][2] = v2; c1[nj][3] = v3;
        mA = fmaxf(mA, fmaxf(v0, v1));
        mB = fmaxf(mB, fmaxf(v2, v3));
    }
    mA = fmaxf(mA, __shfl_xor_sync(0xffffffffu, mA, 1));
    mA = fmaxf(mA, __shfl_xor_sync(0xffffffffu, mA, 2));
    mB = fmaxf(mB, __shfl_xor_sync(0xffffffffu, mB, 1));
    mB = fmaxf(mB, __shfl_xor_sync(0xffffffffu, mB, 2));

    float sA = 0.f, sB = 0.f;
#pragma unroll
    for (int nj = 0; nj < 8; nj++) {
        float e0 = __expf(c1[nj][0] - mA);
        float e1 = __expf(c1[nj][1] - mA);
        float e2 = __expf(c1[nj][2] - mB);
        float e3 = __expf(c1[nj][3] - mB);
        c1[nj][0] = e0; c1[nj][1] = e1; c1[nj][2] = e2; c1[nj][3] = e3;
        sA += e0 + e1; sB += e2 + e3;
    }
    sA += __shfl_xor_sync(0xffffffffu, sA, 1);
    sA += __shfl_xor_sync(0xffffffffu, sA, 2);
    sB += __shfl_xor_sync(0xffffffffu, sB, 1);
    sB += __shfl_xor_sync(0xffffffffu, sB, 2);
    const float invA = 1.f / sA, invB = 1.f / sB;

    float c2[4][4];
#pragma unroll
    for (int nj = 0; nj < 4; nj++)
#pragma unroll
        for (int k = 0; k < 4; k++) c2[nj][k] = 0.f;

#pragma unroll
    for (int k16 = 0; k16 < 4; ++k16) {
        uint32_t a0 = f22u(c1[2*k16][0]   * invA, c1[2*k16][1]   * invA);
        uint32_t a1 = f22u(c1[2*k16][2]   * invB, c1[2*k16][3]   * invB);
        uint32_t a2 = f22u(c1[2*k16+1][0] * invA, c1[2*k16+1][1] * invA);
        uint32_t a3 = f22u(c1[2*k16+1][2] * invB, c1[2*k16+1][3] * invB);
#pragma unroll
        for (int jp = 0; jp < 2; ++jp) {
            uint32_t b00, b10, b01, b11;
            ldsm4t(b00, b10, b01, b11, vAddr + k16 * (16 * APH * 2) + jp * 32);
            mma_f16(c2[2*jp],   a0, a1, a2, a3, b00, b10);
            mma_f16(c2[2*jp+1], a0, a1, a2, a3, b01, b11);
        }
    }

    const size_t obase = (size_t)s * ((size_t)BB * NWIN * PP * CC)
                       + (((size_t)b * NWIN + win) * PP) * CC
                       + (size_t)head * HD;
#pragma unroll
    for (int nj = 0; nj < 4; nj++) {
#pragma unroll
        for (int h2 = 0; h2 < 2; h2++) {
            int row = r0 + g + 8 * h2;
            int col = nj * 8 + t4 * 2;
            __half2 hv = __floats2half2_rn(c2[nj][h2 * 2 + 0], c2[nj][h2 * 2 + 1]);
            *reinterpret_cast<__half2*>(&g_attnh[obase + (size_t)row * CC + col]) = hv;
        }
    }
}

// ---------------------------------------------------------------------------
// Kernel 3: output projection. Chunk-64, launch_bounds(256,2).
// ---------------------------------------------------------------------------
__global__ __launch_bounds__(256, 2)
void proj_mma(const float* __restrict__ bo1, const float* __restrict__ bo2,
              float* __restrict__ out)
{
    extern __shared__ __align__(16) __half sh[];
    const int s = blockIdx.z;
    const float* __restrict__ bo = s ? bo2 : bo1;
    float* __restrict__ dst = out + (size_t)s * ((size_t)BB * HH * WW * OUTC);
    const int colBlock = blockIdx.x;     // 0..1
    const int rowBlock = blockIdx.y;     // 0..1023
    const int tid  = threadIdx.x;
    const int wid  = tid >> 5;
    const int lane = tid & 31;
    const int g    = lane >> 2;
    const int t4   = lane & 3;
    const int lrow = lane & 7;

    const __half* aBase = g_attnh + (size_t)s * ((size_t)BB * NWIN * PP * CC)
                        + (size_t)rowBlock * 128 * 256;
    const __half* bBase = g_wh + 393216 + (size_t)(s * 2 + colBlock) * 32768;

    const uint32_t smemBase = sm_a(sh);
    const int aR0 = tid >> 3, aJ0 = tid & 7;

    const int wrb = (wid & 3) * 32;
    const int wq  = wid >> 2;
    const uint32_t aOff0 = ((wrb + lrow + ((lane >> 3) & 1) * 8) * AP2 + ((lane >> 4) & 1) * 8) * 2;
    const uint32_t aOff1 = aOff0 + 16 * AP2 * 2;
    const uint32_t bfOff = ASTG2 + ((wq * 4) * 32 + lane) * 16;

#define PISSUE(c, st) do {                                                        \
    uint32_t ab = smemBase + (st) * STAGE_BYTES;                                  \
    uint32_t bb = ab + ASTG2;                                                     \
    cpa16(ab + (uint32_t)(aR0 * 9 + aJ0) * 16,        aBase + (aR0      ) * 256 + aJ0 * 8 + (c) * 64); \
    cpa16(ab + (uint32_t)((aR0 + 32) * 9 + aJ0) * 16, aBase + (aR0 + 32 ) * 256 + aJ0 * 8 + (c) * 64); \
    cpa16(ab + (uint32_t)((aR0 + 64) * 9 + aJ0) * 16, aBase + (aR0 + 64 ) * 256 + aJ0 * 8 + (c) * 64); \
    cpa16(ab + (uint32_t)((aR0 + 96) * 9 + aJ0) * 16, aBase + (aR0 + 96 ) * 256 + aJ0 * 8 + (c) * 64); \
    cpa16(bb + (tid      ) * 16, bBase + (size_t)(c) * 8192 + (tid      ) * 8);   \
    cpa16(bb + (tid + 256) * 16, bBase + (size_t)(c) * 8192 + (tid + 256) * 8);   \
    cpa16(bb + (tid + 512) * 16, bBase + (size_t)(c) * 8192 + (tid + 512) * 8);   \
    cpa16(bb + (tid + 768) * 16, bBase + (size_t)(c) * 8192 + (tid + 768) * 8);   \
    CP_COMMIT();                                                                  \
} while (0)

    float acc[2][8][4];
#pragma unroll
    for (int mi = 0; mi < 2; mi++)
#pragma unroll
        for (int nj = 0; nj < 8; nj++)
#pragma unroll
            for (int k = 0; k < 4; k++) acc[mi][nj][k] = 0.f;

    PISSUE(0, 0);
    PISSUE(1, 1);

#pragma unroll
    for (int c = 0; c < 4; ++c) {
        const int st = c % NSTAGE;
        if (c < 3) asm volatile("cp.async.wait_group 1;");
        else       asm volatile("cp.async.wait_group 0;");
        __syncthreads();
        if (c < 2) PISSUE(c + 2, (c + 2) % NSTAGE);

        const uint32_t stb = smemBase + st * STAGE_BYTES;
#pragma unroll
        for (int k16 = 0; k16 < 4; ++k16) {
            uint4 bf[4];
#pragma unroll
            for (int jp = 0; jp < 4; ++jp)
                lds128(bf[jp], stb + bfOff + k16 * 4096 + jp * 512);
            uint32_t a0[2], a1[2], a2[2], a3[2];
            ldsm4(a0[0], a1[0], a2[0], a3[0], stb + aOff0 + k16 * 32);
            ldsm4(a0[1], a1[1], a2[1], a3[1], stb + aOff1 + k16 * 32);
#pragma unroll
            for (int jp = 0; jp < 4; ++jp) {
                const uint4 b = bf[jp];
                mma_f16(acc[0][2*jp],   a0[0], a1[0], a2[0], a3[0], b.x, b.y);
                mma_f16(acc[0][2*jp+1], a0[0], a1[0], a2[0], a3[0], b.z, b.w);
                mma_f16(acc[1][2*jp],   a0[1], a1[1], a2[1], a3[1], b.x, b.y);
                mma_f16(acc[1][2*jp+1], a0[1], a1[1], a2[1], a3[1], b.z, b.w);
            }
        }
    }
#undef PISSUE

    // Epilogue: unwindow + roll scatter (fp32 output)
    const int wcb = wq * 64;
#pragma unroll
    for (int mi = 0; mi < 2; mi++) {
#pragma unroll
        for (int h = 0; h < 2; h++) {
            int r  = rowBlock * 128 + wrb + mi * 16 + g + 8 * h;
            int pr = r & 63, wr = (r >> 6) & 1023, br = r >> 16;
            int hout = (((wr >> 5) << 3) + (pr >> 3) + SHIFT) & 255;
            int wout = ((wr & 31) << 3) + (pr & 7);
            size_t rowbase = (((size_t)br * HH + hout) * WW + wout) * OUTC;
#pragma unroll
            for (int nj = 0; nj < 8; nj++) {
                int n = colBlock * 128 + wcb + nj * 8 + t4 * 2;
                float2 v;
                v.x = acc[mi][nj][h * 2 + 0] + bo[n];
                v.y = acc[mi][nj][h * 2 + 1] + bo[n + 1];
                *reinterpret_cast<float2*>(&dst[rowbase + n]) = v;
            }
        }
    }
}

// ---------------------------------------------------------------------------
// Launch
// ---------------------------------------------------------------------------
extern "C" void kernel_launch(void* const* d_in, const int* in_sizes, int n_in,
                              void* d_out, int out_size)
{
    const float* emb1  = (const float*)d_in[0];
    const float* emb2  = (const float*)d_in[1];
    const float* Wqkv1 = (const float*)d_in[2];
    const float* bqkv1 = (const float*)d_in[3];
    const float* Wqkv2 = (const float*)d_in[4];
    const float* bqkv2 = (const float*)d_in[5];
    const float* rel1  = (const float*)d_in[6];
    const float* rel2  = (const float*)d_in[7];
    const float* Wo1   = (const float*)d_in[8];
    const float* bo1   = (const float*)d_in[9];
    const float* Wo2   = (const float*)d_in[10];
    const float* bo2   = (const float*)d_in[11];
    float* out = (float*)d_out;
    (void)in_sizes; (void)n_in; (void)out_size;

    cudaFuncSetAttribute(qkv_mma,  cudaFuncAttributeMaxDynamicSharedMemorySize, GEMM_SMEM);
    cudaFuncSetAttribute(proj_mma, cudaFuncAttributeMaxDynamicSharedMemorySize, GEMM_SMEM);

    bias_kernel<<<256, 256>>>(rel1, rel2);
    wpack_kernel<<<2048, 256>>>(Wqkv1, Wqkv2, Wo1, Wo2);
    embh_kernel<<<32768, 256>>>(emb1, emb2);

    dim3 gq(6, 1024, 2);
    qkv_mma<<<gq, 256, GEMM_SMEM>>>(bqkv1, bqkv2);

    dim3 ga(2048, 8, 2);
    attn_mma<<<ga, 128>>>();

    dim3 gp(2, 1024, 2);
    proj_mma<<<gp, 256, GEMM_SMEM>>>(bo1, bo2, out);
}